// round 1
// baseline (speedup 1.0000x reference)
#include <cuda_runtime.h>

#define Hh 32
#define Bb 64
#define Tt 16384
#define CHUNK 32
#define NCHUNK (Tt / CHUNK)

// tanh(x) = 1 - 2/(e^{2x}+1), via ex2.approx + rcp.approx (err ~1e-6, lat ~44cyc)
__device__ __forceinline__ float ftanh(float x) {
    float e;
    asm("ex2.approx.f32 %0, %1;" : "=f"(e) : "f"(x * 2.8853900817779268f)); // 2*log2(e)
    float r;
    asm("rcp.approx.f32 %0, %1;" : "=f"(r) : "f"(e + 1.0f));
    return fmaf(-2.0f, r, 1.0f);
}

__global__ __launch_bounds__(128, 1) void rnn_pipe_kernel(
    const float* __restrict__ x,        // [B,T,1]
    const float* __restrict__ h_state,  // [2,B,H]
    const float* __restrict__ W_ih0,    // [H,1]
    const float* __restrict__ W_hh0,    // [H,H]
    const float* __restrict__ b_ih0,    // [H]
    const float* __restrict__ b_hh0,    // [H]
    const float* __restrict__ W_ih1,    // [H,H]
    const float* __restrict__ W_hh1,    // [H,H]
    const float* __restrict__ b_ih1,    // [H]
    const float* __restrict__ b_hh1,    // [H]
    const float* __restrict__ W_out,    // [1,H]
    const float* __restrict__ b_out,    // [1]
    float* __restrict__ out)            // [B*T] outs ++ [2,B,H] h_final
{
    // Double-buffered 32-step rings between pipeline stages
    __shared__ __align__(16) float sh0[2][CHUNK][Hh];      // A  -> B2
    __shared__ __align__(16) float su [2][CHUNK][Hh];      // B2 -> B1
    __shared__ float sh1[2][CHUNK][Hh + 1];                // B1 -> C (padded, conflict-free)

    const int b    = blockIdx.x;
    const int lane = threadIdx.x & 31;
    const int wid  = threadIdx.x >> 5;
    const unsigned FULL = 0xffffffffu;

    if (wid == 0) {
        // ---- Warp A: layer-0 recurrence  h0 = tanh(x*W_ih0 + b0 + W_hh0 h0) ----
        float w[Hh];
        #pragma unroll
        for (int k = 0; k < Hh; ++k) w[k] = W_hh0[lane * Hh + k];
        const float wi = W_ih0[lane];
        const float bj = b_ih0[lane] + b_hh0[lane];
        float h = h_state[b * Hh + lane];

        const float* xb = x + (size_t)b * Tt;
        float xc = xb[lane];                     // chunk 0 of x, lane-distributed
        for (int g = 0; g < NCHUNK + 3; ++g) {
            if (g < NCHUNK) {
                float xn = (g + 1 < NCHUNK) ? xb[(g + 1) * CHUNK + lane] : 0.f; // prefetch
                float (*dst)[Hh] = sh0[g & 1];
                #pragma unroll 1
                for (int s = 0; s < CHUNK; ++s) {
                    float xt = __shfl_sync(FULL, xc, s);
                    float a0 = fmaf(xt, wi, bj);
                    float a1 = 0.f, a2 = 0.f, a3 = 0.f;
                    #pragma unroll
                    for (int k = 0; k < 8; ++k) {
                        a0 = fmaf(w[k],      __shfl_sync(FULL, h, k),      a0);
                        a1 = fmaf(w[k + 8],  __shfl_sync(FULL, h, k + 8),  a1);
                        a2 = fmaf(w[k + 16], __shfl_sync(FULL, h, k + 16), a2);
                        a3 = fmaf(w[k + 24], __shfl_sync(FULL, h, k + 24), a3);
                    }
                    h = ftanh((a0 + a1) + (a2 + a3));
                    dst[s][lane] = h;
                }
                xc = xn;
            }
            __syncthreads();
        }
        out[(size_t)Bb * Tt + b * Hh + lane] = h;                 // h_final layer 0

    } else if (wid == 1) {
        // ---- Warp B2: u(t) = W_ih1 . h0n(t)   (feed-forward, one chunk behind A) ----
        float w[Hh];
        #pragma unroll
        for (int k = 0; k < Hh; ++k) w[k] = W_ih1[lane * Hh + k];
        for (int g = 0; g < NCHUNK + 3; ++g) {
            if (g >= 1 && g <= NCHUNK) {
                int buf = (g - 1) & 1;
                #pragma unroll 1
                for (int s = 0; s < CHUNK; ++s) {
                    const float4* hv = (const float4*)sh0[buf][s];
                    float a0 = 0.f, a1 = 0.f, a2 = 0.f, a3 = 0.f;
                    #pragma unroll
                    for (int q = 0; q < 8; ++q) {
                        float4 v = hv[q];
                        a0 = fmaf(w[4 * q + 0], v.x, a0);
                        a1 = fmaf(w[4 * q + 1], v.y, a1);
                        a2 = fmaf(w[4 * q + 2], v.z, a2);
                        a3 = fmaf(w[4 * q + 3], v.w, a3);
                    }
                    su[buf][s][lane] = (a0 + a1) + (a2 + a3);
                }
            }
            __syncthreads();
        }

    } else if (wid == 2) {
        // ---- Warp B1: layer-1 recurrence  h1 = tanh(u(t) + b1 + W_hh1 h1) ----
        float w[Hh];
        #pragma unroll
        for (int k = 0; k < Hh; ++k) w[k] = W_hh1[lane * Hh + k];
        const float bj = b_ih1[lane] + b_hh1[lane];
        float h = h_state[Bb * Hh + b * Hh + lane];
        for (int g = 0; g < NCHUNK + 3; ++g) {
            if (g >= 2 && g <= NCHUNK + 1) {
                int buf = g & 1;  // (g-2)&1
                #pragma unroll 1
                for (int s = 0; s < CHUNK; ++s) {
                    float a0 = su[buf][s][lane] + bj;
                    float a1 = 0.f, a2 = 0.f, a3 = 0.f;
                    #pragma unroll
                    for (int k = 0; k < 8; ++k) {
                        a0 = fmaf(w[k],      __shfl_sync(FULL, h, k),      a0);
                        a1 = fmaf(w[k + 8],  __shfl_sync(FULL, h, k + 8),  a1);
                        a2 = fmaf(w[k + 16], __shfl_sync(FULL, h, k + 16), a2);
                        a3 = fmaf(w[k + 24], __shfl_sync(FULL, h, k + 24), a3);
                    }
                    h = ftanh((a0 + a1) + (a2 + a3));
                    sh1[buf][s][lane] = h;
                }
            }
            __syncthreads();
        }
        out[(size_t)Bb * Tt + Bb * Hh + b * Hh + lane] = h;       // h_final layer 1

    } else {
        // ---- Warp C: outs(t) = W_out . h1n(t) + b_out, 32 timesteps per chunk ----
        float w[Hh];
        #pragma unroll
        for (int k = 0; k < Hh; ++k) w[k] = W_out[k];
        const float bo = b_out[0];
        float* ob = out + (size_t)b * Tt;
        for (int g = 0; g < NCHUNK + 3; ++g) {
            if (g >= 3) {
                int gg  = g - 3;
                int buf = gg & 1;
                const float* hv = sh1[buf][lane];   // lane = timestep within chunk
                float a0 = 0.f, a1 = 0.f, a2 = 0.f, a3 = 0.f;
                #pragma unroll
                for (int k = 0; k < 8; ++k) {
                    a0 = fmaf(w[k],      hv[k],      a0);
                    a1 = fmaf(w[k + 8],  hv[k + 8],  a1);
                    a2 = fmaf(w[k + 16], hv[k + 16], a2);
                    a3 = fmaf(w[k + 24], hv[k + 24], a3);
                }
                ob[gg * CHUNK + lane] = ((a0 + a1) + (a2 + a3)) + bo;
            }
            __syncthreads();
        }
    }
}

extern "C" void kernel_launch(void* const* d_in, const int* in_sizes, int n_in,
                              void* d_out, int out_size) {
    (void)in_sizes; (void)n_in; (void)out_size;
    rnn_pipe_kernel<<<Bb, 128>>>(
        (const float*)d_in[0],  (const float*)d_in[1],  (const float*)d_in[2],
        (const float*)d_in[3],  (const float*)d_in[4],  (const float*)d_in[5],
        (const float*)d_in[6],  (const float*)d_in[7],  (const float*)d_in[8],
        (const float*)d_in[9],  (const float*)d_in[10], (const float*)d_in[11],
        (float*)d_out);
}

// round 2
// speedup vs baseline: 1.4175x; 1.4175x over previous
#include <cuda_runtime.h>

#define Hh 32
#define Bb 64
#define Tt 16384
#define CHUNK 32
#define NCHUNK (Tt / CHUNK)

// tanh(x) = 1 - 2/(e^{2x}+1), via ex2.approx + rcp.approx (err ~1e-6)
__device__ __forceinline__ float ftanh(float x) {
    float e;
    asm("ex2.approx.f32 %0, %1;" : "=f"(e) : "f"(x * 2.8853900817779268f)); // 2*log2(e)
    float r;
    asm("rcp.approx.f32 %0, %1;" : "=f"(r) : "f"(e + 1.0f));
    return fmaf(-2.0f, r, 1.0f);
}

__global__ __launch_bounds__(128, 1) void rnn_pipe_kernel(
    const float* __restrict__ x,        // [B,T,1]
    const float* __restrict__ h_state,  // [2,B,H]
    const float* __restrict__ W_ih0,    // [H,1]
    const float* __restrict__ W_hh0,    // [H,H]
    const float* __restrict__ b_ih0,    // [H]
    const float* __restrict__ b_hh0,    // [H]
    const float* __restrict__ W_ih1,    // [H,H]
    const float* __restrict__ W_hh1,    // [H,H]
    const float* __restrict__ b_ih1,    // [H]
    const float* __restrict__ b_hh1,    // [H]
    const float* __restrict__ W_out,    // [1,H]
    const float* __restrict__ b_out,    // [1]
    float* __restrict__ out)            // [B*T] outs ++ [2,B,H] h_final
{
    // Double-buffered 32-step rings between pipeline stages
    __shared__ __align__(16) float sh0[2][CHUNK][Hh];      // A  -> B2
    __shared__ __align__(16) float su [2][CHUNK][Hh];      // B2 -> B1
    __shared__ float sh1[2][CHUNK][Hh + 1];                // B1 -> C (padded, conflict-free)
    // Per-warp single-step h exchange buffers (broadcast-read)
    __shared__ __align__(16) float hx0[Hh];                // warp A
    __shared__ __align__(16) float hx1[Hh];                // warp B1

    const int b    = blockIdx.x;
    const int lane = threadIdx.x & 31;
    const int wid  = threadIdx.x >> 5;
    const unsigned FULL = 0xffffffffu;

    if (wid == 0) {
        // ---- Warp A: layer-0 recurrence  h0 = tanh(x*W_ih0 + b0 + W_hh0 h0) ----
        float w[Hh];
        #pragma unroll
        for (int k = 0; k < Hh; ++k) w[k] = W_hh0[lane * Hh + k];
        const float wi = W_ih0[lane];
        const float bj = b_ih0[lane] + b_hh0[lane];
        float h = h_state[b * Hh + lane];

        const float* xb = x + (size_t)b * Tt;
        float xc = xb[lane];                     // chunk 0 of x, lane-distributed
        for (int g = 0; g < NCHUNK + 3; ++g) {
            if (g < NCHUNK) {
                float xn = (g + 1 < NCHUNK) ? xb[(g + 1) * CHUNK + lane] : 0.f; // prefetch
                float (*dst)[Hh] = sh0[g & 1];
                const float4* hv = (const float4*)hx0;
                #pragma unroll 1
                for (int s = 0; s < CHUNK; ++s) {
                    float xt = __shfl_sync(FULL, xc, s);
                    hx0[lane] = h;               // broadcast h via smem (not shfl)
                    __syncwarp();
                    float a0 = fmaf(xt, wi, bj);
                    float a1 = 0.f, a2 = 0.f, a3 = 0.f;
                    #pragma unroll
                    for (int q = 0; q < 8; ++q) {
                        float4 v = hv[q];        // all lanes same addr -> broadcast
                        a0 = fmaf(w[4 * q + 0], v.x, a0);
                        a1 = fmaf(w[4 * q + 1], v.y, a1);
                        a2 = fmaf(w[4 * q + 2], v.z, a2);
                        a3 = fmaf(w[4 * q + 3], v.w, a3);
                    }
                    h = ftanh((a0 + a1) + (a2 + a3));
                    dst[s][lane] = h;
                }
                xc = xn;
            }
            __syncthreads();
        }
        out[(size_t)Bb * Tt + b * Hh + lane] = h;                 // h_final layer 0

    } else if (wid == 1) {
        // ---- Warp B2: u(t) = W_ih1 . h0n(t)   (feed-forward, one chunk behind A) ----
        float w[Hh];
        #pragma unroll
        for (int k = 0; k < Hh; ++k) w[k] = W_ih1[lane * Hh + k];
        for (int g = 0; g < NCHUNK + 3; ++g) {
            if (g >= 1 && g <= NCHUNK) {
                int buf = (g - 1) & 1;
                #pragma unroll 1
                for (int s = 0; s < CHUNK; ++s) {
                    const float4* hv = (const float4*)sh0[buf][s];
                    float a0 = 0.f, a1 = 0.f, a2 = 0.f, a3 = 0.f;
                    #pragma unroll
                    for (int q = 0; q < 8; ++q) {
                        float4 v = hv[q];
                        a0 = fmaf(w[4 * q + 0], v.x, a0);
                        a1 = fmaf(w[4 * q + 1], v.y, a1);
                        a2 = fmaf(w[4 * q + 2], v.z, a2);
                        a3 = fmaf(w[4 * q + 3], v.w, a3);
                    }
                    su[buf][s][lane] = (a0 + a1) + (a2 + a3);
                }
            }
            __syncthreads();
        }

    } else if (wid == 2) {
        // ---- Warp B1: layer-1 recurrence  h1 = tanh(u(t) + b1 + W_hh1 h1) ----
        float w[Hh];
        #pragma unroll
        for (int k = 0; k < Hh; ++k) w[k] = W_hh1[lane * Hh + k];
        const float bj = b_ih1[lane] + b_hh1[lane];
        float h = h_state[Bb * Hh + b * Hh + lane];
        const float4* hv = (const float4*)hx1;
        for (int g = 0; g < NCHUNK + 3; ++g) {
            if (g >= 2 && g <= NCHUNK + 1) {
                int buf = g & 1;  // (g-2)&1
                #pragma unroll 1
                for (int s = 0; s < CHUNK; ++s) {
                    hx1[lane] = h;               // broadcast h via smem
                    __syncwarp();
                    float a0 = su[buf][s][lane] + bj;
                    float a1 = 0.f, a2 = 0.f, a3 = 0.f;
                    #pragma unroll
                    for (int q = 0; q < 8; ++q) {
                        float4 v = hv[q];
                        a0 = fmaf(w[4 * q + 0], v.x, a0);
                        a1 = fmaf(w[4 * q + 1], v.y, a1);
                        a2 = fmaf(w[4 * q + 2], v.z, a2);
                        a3 = fmaf(w[4 * q + 3], v.w, a3);
                    }
                    h = ftanh((a0 + a1) + (a2 + a3));
                    sh1[buf][s][lane] = h;
                }
            }
            __syncthreads();
        }
        out[(size_t)Bb * Tt + Bb * Hh + b * Hh + lane] = h;       // h_final layer 1

    } else {
        // ---- Warp C: outs(t) = W_out . h1n(t) + b_out, 32 timesteps per chunk ----
        float w[Hh];
        #pragma unroll
        for (int k = 0; k < Hh; ++k) w[k] = W_out[k];
        const float bo = b_out[0];
        float* ob = out + (size_t)b * Tt;
        for (int g = 0; g < NCHUNK + 3; ++g) {
            if (g >= 3) {
                int gg  = g - 3;
                int buf = gg & 1;
                const float* hv = sh1[buf][lane];   // lane = timestep within chunk
                float a0 = 0.f, a1 = 0.f, a2 = 0.f, a3 = 0.f;
                #pragma unroll
                for (int k = 0; k < 8; ++k) {
                    a0 = fmaf(w[k],      hv[k],      a0);
                    a1 = fmaf(w[k + 8],  hv[k + 8],  a1);
                    a2 = fmaf(w[k + 16], hv[k + 16], a2);
                    a3 = fmaf(w[k + 24], hv[k + 24], a3);
                }
                ob[gg * CHUNK + lane] = ((a0 + a1) + (a2 + a3)) + bo;
            }
            __syncthreads();
        }
    }
}

extern "C" void kernel_launch(void* const* d_in, const int* in_sizes, int n_in,
                              void* d_out, int out_size) {
    (void)in_sizes; (void)n_in; (void)out_size;
    rnn_pipe_kernel<<<Bb, 128>>>(
        (const float*)d_in[0],  (const float*)d_in[1],  (const float*)d_in[2],
        (const float*)d_in[3],  (const float*)d_in[4],  (const float*)d_in[5],
        (const float*)d_in[6],  (const float*)d_in[7],  (const float*)d_in[8],
        (const float*)d_in[9],  (const float*)d_in[10], (const float*)d_in[11],
        (float*)d_out);
}

// round 3
// speedup vs baseline: 1.5062x; 1.0626x over previous
#include <cuda_runtime.h>

#define Hh 32
#define Bb 64
#define Tt 16384
#define CHUNK 32
#define NCHUNK (Tt / CHUNK)
#define S1 2.8853900817779268f   /* 2*log2(e) */

__device__ __forceinline__ unsigned long long pk2(float lo, float hi) {
    unsigned long long d; asm("mov.b64 %0,{%1,%2};" : "=l"(d) : "f"(lo), "f"(hi)); return d;
}
__device__ __forceinline__ void upk2(unsigned long long v, float& lo, float& hi) {
    asm("mov.b64 {%0,%1},%2;" : "=f"(lo), "=f"(hi) : "l"(v));
}
__device__ __forceinline__ unsigned long long ffma2(unsigned long long a, unsigned long long b, unsigned long long c) {
    unsigned long long d; asm("fma.rn.f32x2 %0,%1,%2,%3;" : "=l"(d) : "l"(a), "l"(b), "l"(c)); return d;
}
__device__ __forceinline__ unsigned long long fadd2(unsigned long long a, unsigned long long b) {
    unsigned long long d; asm("add.rn.f32x2 %0,%1,%2;" : "=l"(d) : "l"(a), "l"(b)); return d;
}

// 32-float dot against packed pre-scaled weights, operand vector at smem addr (16B aligned).
__device__ __forceinline__ float dot32(unsigned int a, const unsigned long long* w2) {
    unsigned long long p0,p1,p2,p3,p4,p5,p6,p7,p8,p9,pa,pb,pc,pd,pe,pf;
    asm volatile("ld.shared.v2.u64 {%0,%1},[%2];"    : "=l"(p0), "=l"(p1) : "r"(a));
    asm volatile("ld.shared.v2.u64 {%0,%1},[%2+16];" : "=l"(p2), "=l"(p3) : "r"(a));
    asm volatile("ld.shared.v2.u64 {%0,%1},[%2+32];" : "=l"(p4), "=l"(p5) : "r"(a));
    asm volatile("ld.shared.v2.u64 {%0,%1},[%2+48];" : "=l"(p6), "=l"(p7) : "r"(a));
    asm volatile("ld.shared.v2.u64 {%0,%1},[%2+64];" : "=l"(p8), "=l"(p9) : "r"(a));
    asm volatile("ld.shared.v2.u64 {%0,%1},[%2+80];" : "=l"(pa), "=l"(pb) : "r"(a));
    asm volatile("ld.shared.v2.u64 {%0,%1},[%2+96];" : "=l"(pc), "=l"(pd) : "r"(a));
    asm volatile("ld.shared.v2.u64 {%0,%1},[%2+112];": "=l"(pe), "=l"(pf) : "r"(a));
    unsigned long long a0 = 0ull, a1 = 0ull, a2 = 0ull, a3 = 0ull;
    a0 = ffma2(w2[0],  p0, a0); a1 = ffma2(w2[1],  p1, a1);
    a2 = ffma2(w2[2],  p2, a2); a3 = ffma2(w2[3],  p3, a3);
    a0 = ffma2(w2[4],  p4, a0); a1 = ffma2(w2[5],  p5, a1);
    a2 = ffma2(w2[6],  p6, a2); a3 = ffma2(w2[7],  p7, a3);
    a0 = ffma2(w2[8],  p8, a0); a1 = ffma2(w2[9],  p9, a1);
    a2 = ffma2(w2[10], pa, a2); a3 = ffma2(w2[11], pb, a3);
    a0 = ffma2(w2[12], pc, a0); a1 = ffma2(w2[13], pd, a1);
    a2 = ffma2(w2[14], pe, a2); a3 = ffma2(w2[15], pf, a3);
    unsigned long long s = fadd2(fadd2(a0, a1), fadd2(a2, a3));
    float lo, hi; upk2(s, lo, hi);
    return lo + hi;
}

// Exchange r via smem then dot. STS and LDS are all asm volatile -> mutual order kept;
// 32-lane STS is one wavefront, later LDS wavefronts in the in-order smem pipe see it.
__device__ __forceinline__ float rec_dot(unsigned int hxa, int lane, float r, const unsigned long long* w2) {
    asm volatile("st.shared.f32 [%0], %1;" :: "r"(hxa + lane * 4), "f"(r));
    return dot32(hxa, w2);
}

__device__ __forceinline__ float sigm_neg(float arg) {   // r = 1/(exp2(arg)+1), arg pre-scaled
    float e; asm("ex2.approx.f32 %0,%1;" : "=f"(e) : "f"(arg));
    float r; asm("rcp.approx.f32 %0,%1;" : "=f"(r) : "f"(e + 1.0f));
    return r;
}

__global__ __launch_bounds__(128, 1) void rnn_pipe_kernel(
    const float* __restrict__ x,        const float* __restrict__ h_state,
    const float* __restrict__ W_ih0,    const float* __restrict__ W_hh0,
    const float* __restrict__ b_ih0,    const float* __restrict__ b_hh0,
    const float* __restrict__ W_ih1,    const float* __restrict__ W_hh1,
    const float* __restrict__ b_ih1,    const float* __restrict__ b_hh1,
    const float* __restrict__ W_out,    const float* __restrict__ b_out,
    float* __restrict__ out)
{
    __shared__ __align__(16) float sh0[2][CHUNK][Hh];   // A  -> B2  (r0 values)
    __shared__ __align__(16) float su [2][CHUNK][Hh];   // B2 -> B1  (s1-scaled u)
    __shared__ float sh1[2][CHUNK][Hh + 1];             // B1 -> C   (r1, padded)
    __shared__ __align__(16) float hx0[Hh];             // warp A step exchange
    __shared__ __align__(16) float hx1[Hh];             // warp B1 step exchange

    const int b    = blockIdx.x;
    const int lane = threadIdx.x & 31;
    const int wid  = threadIdx.x >> 5;
    const unsigned FULL = 0xffffffffu;
    const float m = -2.0f * S1;

    if (wid == 0) {
        // ---- Warp A: layer-0 recurrence, exchanges r0 = 1/(e^{2z0}+1) ----
        unsigned long long w2[16];
        float rs = 0.f;
        #pragma unroll
        for (int k = 0; k < 16; ++k) {
            float u0 = W_hh0[lane * Hh + 2 * k], u1 = W_hh0[lane * Hh + 2 * k + 1];
            rs += u0 + u1;
            w2[k] = pk2(m * u0, m * u1);
        }
        const float wis   = W_ih0[lane] * S1;
        const float bias2 = S1 * (b_ih0[lane] + b_hh0[lane] + rs);
        float r = fmaf(-0.5f, h_state[b * Hh + lane], 0.5f);
        unsigned int hx0a = (unsigned int)__cvta_generic_to_shared(hx0);

        const float* xb = x + (size_t)b * Tt;
        float xc = xb[lane];
        for (int g = 0; g < NCHUNK + 3; ++g) {
            if (g < NCHUNK) {
                float xn = (g + 1 < NCHUNK) ? xb[(g + 1) * CHUNK + lane] : 0.f;
                float (*dst)[Hh] = sh0[g & 1];
                #pragma unroll 1
                for (int s = 0; s < CHUNK; ++s) {
                    float xt = __shfl_sync(FULL, xc, s);
                    float xterm = fmaf(xt, wis, bias2);          // off-chain
                    float d = rec_dot(hx0a, lane, r, w2);
                    r = sigm_neg(d + xterm);
                    dst[s][lane] = r;
                }
                xc = xn;
            }
            __syncthreads();
        }
        out[(size_t)Bb * Tt + b * Hh + lane] = fmaf(-2.f, r, 1.f);   // h_final L0

    } else if (wid == 1) {
        // ---- Warp B2: u'(t) = S1*(rowsum + W_ih1 . h0) from r0 ring ----
        unsigned long long w2[16];
        float rs = 0.f;
        #pragma unroll
        for (int k = 0; k < 16; ++k) {
            float u0 = W_ih1[lane * Hh + 2 * k], u1 = W_ih1[lane * Hh + 2 * k + 1];
            rs += u0 + u1;
            w2[k] = pk2(m * u0, m * u1);
        }
        const float seed = S1 * rs;
        unsigned int s0a = (unsigned int)__cvta_generic_to_shared(sh0);
        for (int g = 0; g < NCHUNK + 3; ++g) {
            if (g >= 1 && g <= NCHUNK) {
                int buf = (g - 1) & 1;
                unsigned int base = s0a + buf * (CHUNK * Hh * 4);
                #pragma unroll 1
                for (int s = 0; s < CHUNK; ++s) {
                    float d = dot32(base + s * (Hh * 4), w2);
                    su[buf][s][lane] = d + seed;
                }
            }
            __syncthreads();
        }

    } else if (wid == 2) {
        // ---- Warp B1: layer-1 recurrence, exchanges r1 ----
        unsigned long long w2[16];
        float rs = 0.f;
        #pragma unroll
        for (int k = 0; k < 16; ++k) {
            float u0 = W_hh1[lane * Hh + 2 * k], u1 = W_hh1[lane * Hh + 2 * k + 1];
            rs += u0 + u1;
            w2[k] = pk2(m * u0, m * u1);
        }
        const float bias1 = S1 * (b_ih1[lane] + b_hh1[lane] + rs);
        float r = fmaf(-0.5f, h_state[Bb * Hh + b * Hh + lane], 0.5f);
        unsigned int hx1a = (unsigned int)__cvta_generic_to_shared(hx1);
        for (int g = 0; g < NCHUNK + 3; ++g) {
            if (g >= 2 && g <= NCHUNK + 1) {
                int buf = g & 1;  // (g-2)&1
                #pragma unroll 1
                for (int s = 0; s < CHUNK; ++s) {
                    float uv = su[buf][s][lane] + bias1;          // off-chain
                    float d = rec_dot(hx1a, lane, r, w2);
                    r = sigm_neg(d + uv);
                    sh1[buf][s][lane] = r;
                }
            }
            __syncthreads();
        }
        out[(size_t)Bb * Tt + Bb * Hh + b * Hh + lane] = fmaf(-2.f, r, 1.f);  // h_final L1

    } else {
        // ---- Warp C: outs(t) = (b_out + rowsum) - 2*W_out . r1 ----
        float wc[Hh];
        float csum = b_out[0];
        #pragma unroll
        for (int k = 0; k < Hh; ++k) { float w = W_out[k]; csum += w; wc[k] = -2.f * w; }
        float* ob = out + (size_t)b * Tt;
        for (int g = 0; g < NCHUNK + 3; ++g) {
            if (g >= 3) {
                int gg  = g - 3;
                int buf = gg & 1;
                const float* hv = sh1[buf][lane];
                float a0 = 0.f, a1 = 0.f, a2 = 0.f, a3 = 0.f;
                #pragma unroll
                for (int k = 0; k < 8; ++k) {
                    a0 = fmaf(wc[k],      hv[k],      a0);
                    a1 = fmaf(wc[k + 8],  hv[k + 8],  a1);
                    a2 = fmaf(wc[k + 16], hv[k + 16], a2);
                    a3 = fmaf(wc[k + 24], hv[k + 24], a3);
                }
                ob[gg * CHUNK + lane] = (((a0 + a1) + (a2 + a3)) + csum);
            }
            __syncthreads();
        }
    }
}

extern "C" void kernel_launch(void* const* d_in, const int* in_sizes, int n_in,
                              void* d_out, int out_size) {
    (void)in_sizes; (void)n_in; (void)out_size;
    rnn_pipe_kernel<<<Bb, 128>>>(
        (const float*)d_in[0],  (const float*)d_in[1],  (const float*)d_in[2],
        (const float*)d_in[3],  (const float*)d_in[4],  (const float*)d_in[5],
        (const float*)d_in[6],  (const float*)d_in[7],  (const float*)d_in[8],
        (const float*)d_in[9],  (const float*)d_in[10], (const float*)d_in[11],
        (float*)d_out);
}

// round 4
// speedup vs baseline: 1.6266x; 1.0800x over previous
#include <cuda_runtime.h>

#define Hh 32
#define Bb 64
#define Tt 16384
#define CHUNK 32
#define NCHUNK (Tt / CHUNK)
#define S1 2.8853900817779268f   /* 2*log2(e) */

__device__ __forceinline__ unsigned long long pk2(float lo, float hi) {
    unsigned long long d; asm("mov.b64 %0,{%1,%2};" : "=l"(d) : "f"(lo), "f"(hi)); return d;
}
__device__ __forceinline__ void upk2(unsigned long long v, float& lo, float& hi) {
    asm("mov.b64 {%0,%1},%2;" : "=f"(lo), "=f"(hi) : "l"(v));
}
__device__ __forceinline__ unsigned long long ffma2(unsigned long long a, unsigned long long b, unsigned long long c) {
    unsigned long long d; asm("fma.rn.f32x2 %0,%1,%2,%3;" : "=l"(d) : "l"(a), "l"(b), "l"(c)); return d;
}
__device__ __forceinline__ unsigned long long fadd2(unsigned long long a, unsigned long long b) {
    unsigned long long d; asm("add.rn.f32x2 %0,%1,%2;" : "=l"(d) : "l"(a), "l"(b)); return d;
}

// 32-float dot vs packed pre-scaled weights; seed folded into accumulator 0.
// Operand vector at smem address a (16B aligned), broadcast-read.
__device__ __forceinline__ float dot32s(unsigned int a, const unsigned long long* w2, float seed) {
    unsigned long long p0,p1,p2,p3,p4,p5,p6,p7,p8,p9,pa,pb,pc,pd,pe,pf;
    asm volatile("ld.shared.v2.u64 {%0,%1},[%2];"    : "=l"(p0), "=l"(p1) : "r"(a));
    asm volatile("ld.shared.v2.u64 {%0,%1},[%2+16];" : "=l"(p2), "=l"(p3) : "r"(a));
    asm volatile("ld.shared.v2.u64 {%0,%1},[%2+32];" : "=l"(p4), "=l"(p5) : "r"(a));
    asm volatile("ld.shared.v2.u64 {%0,%1},[%2+48];" : "=l"(p6), "=l"(p7) : "r"(a));
    asm volatile("ld.shared.v2.u64 {%0,%1},[%2+64];" : "=l"(p8), "=l"(p9) : "r"(a));
    asm volatile("ld.shared.v2.u64 {%0,%1},[%2+80];" : "=l"(pa), "=l"(pb) : "r"(a));
    asm volatile("ld.shared.v2.u64 {%0,%1},[%2+96];" : "=l"(pc), "=l"(pd) : "r"(a));
    asm volatile("ld.shared.v2.u64 {%0,%1},[%2+112];": "=l"(pe), "=l"(pf) : "r"(a));
    unsigned long long a0 = pk2(seed, 0.f), a1 = 0ull, a2 = 0ull, a3 = 0ull;
    a0 = ffma2(w2[0],  p0, a0); a1 = ffma2(w2[1],  p1, a1);
    a2 = ffma2(w2[2],  p2, a2); a3 = ffma2(w2[3],  p3, a3);
    a0 = ffma2(w2[4],  p4, a0); a1 = ffma2(w2[5],  p5, a1);
    a2 = ffma2(w2[6],  p6, a2); a3 = ffma2(w2[7],  p7, a3);
    a0 = ffma2(w2[8],  p8, a0); a1 = ffma2(w2[9],  p9, a1);
    a2 = ffma2(w2[10], pa, a2); a3 = ffma2(w2[11], pb, a3);
    a0 = ffma2(w2[12], pc, a0); a1 = ffma2(w2[13], pd, a1);
    a2 = ffma2(w2[14], pe, a2); a3 = ffma2(w2[15], pf, a3);
    unsigned long long s = fadd2(fadd2(a0, a1), fadd2(a2, a3));
    float lo, hi; upk2(s, lo, hi);
    return lo + hi;
}

// r = 1/(exp2(arg)+1), arg pre-scaled by 2*log2(e)
__device__ __forceinline__ float sigm_neg(float arg) {
    float e; asm("ex2.approx.f32 %0,%1;" : "=f"(e) : "f"(arg));
    float r; asm("rcp.approx.f32 %0,%1;" : "=f"(r) : "f"(e + 1.0f));
    return r;
}

// One recurrent step: publish r to hx, dot with seed, activate.
__device__ __forceinline__ float rstep(unsigned int hxa, int lane, float r,
                                       const unsigned long long* w2, float seed) {
    asm volatile("st.shared.f32 [%0], %1;" :: "r"(hxa + lane * 4), "f"(r));
    return sigm_neg(dot32s(hxa, w2, seed));
}

__global__ __launch_bounds__(128, 1) void rnn_pipe_kernel(
    const float* __restrict__ x,        const float* __restrict__ h_state,
    const float* __restrict__ W_ih0,    const float* __restrict__ W_hh0,
    const float* __restrict__ b_ih0,    const float* __restrict__ b_hh0,
    const float* __restrict__ W_ih1,    const float* __restrict__ W_hh1,
    const float* __restrict__ b_ih1,    const float* __restrict__ b_hh1,
    const float* __restrict__ W_out,    const float* __restrict__ b_out,
    float* __restrict__ out)
{
    __shared__ __align__(16) float sh0[2][CHUNK][Hh];   // A  -> B2  (r0 values)
    __shared__ __align__(16) float su [2][CHUNK][Hh];   // B2 -> B1  (scaled u + rowsum)
    __shared__ float sh1[2][CHUNK][Hh + 1];             // B1 -> C   (r1, padded)
    __shared__ __align__(16) float hx0[Hh];             // warp A step exchange
    __shared__ __align__(16) float hx1[Hh];             // warp B1 step exchange

    const int b    = blockIdx.x;
    const int lane = threadIdx.x & 31;
    const int wid  = threadIdx.x >> 5;
    const unsigned FULL = 0xffffffffu;
    const float m = -2.0f * S1;

    if (wid == 0) {
        // ---- Warp A: layer-0 recurrence, exchanges r0 = 1/(e^{2z0}+1) ----
        unsigned long long w2[16];
        float rs = 0.f;
        #pragma unroll
        for (int k = 0; k < 16; ++k) {
            float u0 = W_hh0[lane * Hh + 2 * k], u1 = W_hh0[lane * Hh + 2 * k + 1];
            rs += u0 + u1;
            w2[k] = pk2(m * u0, m * u1);
        }
        const float wis   = W_ih0[lane] * S1;
        const float bias2 = S1 * (b_ih0[lane] + b_hh0[lane] + rs);
        float r = fmaf(-0.5f, h_state[b * Hh + lane], 0.5f);
        unsigned int hx0a = (unsigned int)__cvta_generic_to_shared(hx0);

        const float* xb = x + (size_t)b * Tt;
        float xc = xb[lane];
        for (int g = 0; g < NCHUNK + 3; ++g) {
            if (g < NCHUNK) {
                float xn = (g + 1 < NCHUNK) ? xb[(g + 1) * CHUNK + lane] : 0.f;
                float (*dst)[Hh] = sh0[g & 1];
                #pragma unroll 4
                for (int s = 0; s < CHUNK; ++s) {
                    float xterm = fmaf(__shfl_sync(FULL, xc, s), wis, bias2); // off-chain
                    r = rstep(hx0a, lane, r, w2, xterm);
                    dst[s][lane] = r;
                }
                xc = xn;
            }
            __syncthreads();
        }
        out[(size_t)Bb * Tt + b * Hh + lane] = fmaf(-2.f, r, 1.f);   // h_final L0

    } else if (wid == 1) {
        // ---- Warp B2: u'(t) = S1*(rowsum + W_ih1 . h0) from r0 ring ----
        unsigned long long w2[16];
        float rs = 0.f;
        #pragma unroll
        for (int k = 0; k < 16; ++k) {
            float u0 = W_ih1[lane * Hh + 2 * k], u1 = W_ih1[lane * Hh + 2 * k + 1];
            rs += u0 + u1;
            w2[k] = pk2(m * u0, m * u1);
        }
        const float seed = S1 * rs;
        unsigned int s0a = (unsigned int)__cvta_generic_to_shared(sh0);
        for (int g = 0; g < NCHUNK + 3; ++g) {
            if (g >= 1 && g <= NCHUNK) {
                int buf = (g - 1) & 1;
                unsigned int base = s0a + buf * (CHUNK * Hh * 4);
                #pragma unroll 4
                for (int s = 0; s < CHUNK; ++s) {
                    su[buf][s][lane] = dot32s(base + s * (Hh * 4), w2, seed);
                }
            }
            __syncthreads();
        }

    } else if (wid == 2) {
        // ---- Warp B1: layer-1 recurrence, exchanges r1 ----
        unsigned long long w2[16];
        float rs = 0.f;
        #pragma unroll
        for (int k = 0; k < 16; ++k) {
            float u0 = W_hh1[lane * Hh + 2 * k], u1 = W_hh1[lane * Hh + 2 * k + 1];
            rs += u0 + u1;
            w2[k] = pk2(m * u0, m * u1);
        }
        const float bias1 = S1 * (b_ih1[lane] + b_hh1[lane] + rs);
        float r = fmaf(-0.5f, h_state[Bb * Hh + b * Hh + lane], 0.5f);
        unsigned int hx1a = (unsigned int)__cvta_generic_to_shared(hx1);
        for (int g = 0; g < NCHUNK + 3; ++g) {
            if (g >= 2 && g <= NCHUNK + 1) {
                int buf = g & 1;  // (g-2)&1
                #pragma unroll 4
                for (int s = 0; s < CHUNK; ++s) {
                    float uv = su[buf][s][lane] + bias1;          // off-chain, hoistable
                    r = rstep(hx1a, lane, r, w2, uv);
                    sh1[buf][s][lane] = r;
                }
            }
            __syncthreads();
        }
        out[(size_t)Bb * Tt + Bb * Hh + b * Hh + lane] = fmaf(-2.f, r, 1.f);  // h_final L1

    } else {
        // ---- Warp C: outs(t) = (b_out + rowsum) - 2*W_out . r1 ----
        float wc[Hh];
        float csum = b_out[0];
        #pragma unroll
        for (int k = 0; k < Hh; ++k) { float w = W_out[k]; csum += w; wc[k] = -2.f * w; }
        float* ob = out + (size_t)b * Tt;
        for (int g = 0; g < NCHUNK + 3; ++g) {
            if (g >= 3) {
                int gg  = g - 3;
                int buf = gg & 1;
                const float* hv = sh1[buf][lane];
                float a0 = 0.f, a1 = 0.f, a2 = 0.f, a3 = 0.f;
                #pragma unroll
                for (int k = 0; k < 8; ++k) {
                    a0 = fmaf(wc[k],      hv[k],      a0);
                    a1 = fmaf(wc[k + 8],  hv[k + 8],  a1);
                    a2 = fmaf(wc[k + 16], hv[k + 16], a2);
                    a3 = fmaf(wc[k + 24], hv[k + 24], a3);
                }
                ob[gg * CHUNK + lane] = (((a0 + a1) + (a2 + a3)) + csum);
            }
            __syncthreads();
        }
    }
}

extern "C" void kernel_launch(void* const* d_in, const int* in_sizes, int n_in,
                              void* d_out, int out_size) {
    (void)in_sizes; (void)n_in; (void)out_size;
    rnn_pipe_kernel<<<Bb, 128>>>(
        (const float*)d_in[0],  (const float*)d_in[1],  (const float*)d_in[2],
        (const float*)d_in[3],  (const float*)d_in[4],  (const float*)d_in[5],
        (const float*)d_in[6],  (const float*)d_in[7],  (const float*)d_in[8],
        (const float*)d_in[9],  (const float*)d_in[10], (const float*)d_in[11],
        (float*)d_out);
}